// round 4
// baseline (speedup 1.0000x reference)
#include <cuda_runtime.h>
#include <cuda_bf16.h>
#include <math.h>
#include <stdint.h>

#define DIM 256
#define HEADS 8
#define WS 8
#define B_ 8
#define NTOK (B_*128*128)          // 131072
#define MLP_HIDDEN 1024
#define SCALE_ 0.17677669529663687f

// ---------------- scratch ----------------
__device__ float g_qkv [NTOK * 768];
__device__ float g_attn[NTOK * DIM];          // also reused as rounded-x before step 2
__device__ float g_x   [NTOK * DIM];
__device__ float g_ln  [NTOK * DIM];
__device__ float g_h   [NTOK * MLP_HIDDEN];
__device__ float g_pool [B_ * 256 * DIM];
__device__ float g_qkvg [B_ * 256 * 768];
__device__ float g_attng[B_ * 256 * DIM];
__device__ float g_wr  [1048576];             // rounded weights (see offsets below)

// weight offsets inside g_wr
#define OFF_QKVW  0
#define OFF_PROJW 196608
#define OFF_PROJ2W 262144
#define OFF_FC1W  327680
#define OFF_FC2W  589824
#define OFF_QKV2W 851968

// ---------------- helpers ----------------
__device__ __forceinline__ uint32_t f2tf32(float f) {
    uint32_t u;
    asm("cvt.rna.tf32.f32 %0, %1;" : "=r"(u) : "f"(f));
    return u;
}
__device__ __forceinline__ float rnd_tf32(float f) {
    return __uint_as_float(f2tf32(f));
}
__device__ __forceinline__ void mma_tf32(float* d, float a0, float a1, float a2, float a3,
                                         float b0, float b1) {
    asm volatile(
        "mma.sync.aligned.m16n8k8.row.col.f32.tf32.tf32.f32 "
        "{%0,%1,%2,%3}, {%4,%5,%6,%7}, {%8,%9}, {%0,%1,%2,%3};"
        : "+f"(d[0]), "+f"(d[1]), "+f"(d[2]), "+f"(d[3])
        : "r"(__float_as_uint(a0)), "r"(__float_as_uint(a1)),
          "r"(__float_as_uint(a2)), "r"(__float_as_uint(a3)),
          "r"(__float_as_uint(b0)), "r"(__float_as_uint(b1)));
}

// ---------------- tf32 round kernel (vectorized) ----------------
__global__ __launch_bounds__(256)
void round4_k(const float4* __restrict__ in, float4* __restrict__ out, int n4)
{
    int i = blockIdx.x * 256 + threadIdx.x;
    if (i < n4) {
        float4 v = in[i];
        v.x = rnd_tf32(v.x); v.y = rnd_tf32(v.y);
        v.z = rnd_tf32(v.z); v.w = rnd_tf32(v.w);
        out[i] = v;
    }
}

// ---------------- tf32 mma.sync GEMM v2 ----------------------------------------
// C[M,N] = A[M,K] @ B[N,K]^T + bias (+epi). Inputs A,B pre-rounded to tf32.
// Phase-split smem: element (row, k) at [row*36 + (k%4)*8 + k/4]
// EPI: 0 none, 1 +res, 2 gelu(exact, rounded output)
#define BM 128
#define BN 128
#define BK 32
#define SPITCH 36
#define TILE_F (128*SPITCH)
#define MGEMM_SMEM (4*TILE_F*4)     // 2 bufs x (A+B) = 73728 bytes

template<int EPI>
__global__ __launch_bounds__(256)
void mgemm_k(const float* __restrict__ A, const float* __restrict__ Bw,
             const float* __restrict__ bias, const float* __restrict__ res,
             float* __restrict__ C, int M, int N, int K)
{
    extern __shared__ float sm[];

    const int t = threadIdx.x, lane = t & 31, warp = t >> 5;
    const int wm = warp >> 1, wn = warp & 1;
    const int bm = blockIdx.x * BM, bn = blockIdx.y * BN;
    const int nk = K / BK;
    const int r = lane >> 2, cq = lane & 3;

    // loader mapping: each thread owns half a row (16 k-values)
    const int lrow = t >> 1;
    const int lhalf = t & 1;
    const float* Agp = A  + (size_t)(bm + lrow) * K + lhalf * 16;
    const float* Bgp = Bw + (size_t)(bn + lrow) * K + lhalf * 16;

    float acc[2][8][4];
#pragma unroll
    for (int i = 0; i < 2; i++)
#pragma unroll
        for (int j = 0; j < 8; j++)
#pragma unroll
            for (int q = 0; q < 4; q++) acc[i][j][q] = 0.f;

    float4 va[4], vb[4];
    const float* vaf = (const float*)va;
    const float* vbf = (const float*)vb;

    // fetch k-tile kt into registers
    auto fetch = [&](int kt) {
#pragma unroll
        for (int c = 0; c < 4; c++) {
            va[c] = *(const float4*)(Agp + kt * BK + c * 4);
            vb[c] = *(const float4*)(Bgp + kt * BK + c * 4);
        }
    };
    // store registers into smem buffer (phase-split transpose)
    auto sts = [&](int buf) {
        float* dA = sm + buf * 2 * TILE_F + lrow * SPITCH + lhalf * 4;
        float* dB = dA + TILE_F;
#pragma unroll
        for (int p = 0; p < 4; p++) {
            *(float4*)(dA + p * 8) = make_float4(vaf[0*4+p], vaf[1*4+p], vaf[2*4+p], vaf[3*4+p]);
            *(float4*)(dB + p * 8) = make_float4(vbf[0*4+p], vbf[1*4+p], vbf[2*4+p], vbf[3*4+p]);
        }
    };

    fetch(0);
    sts(0);
    __syncthreads();

    int buf = 0;
    for (int kt = 0; kt < nk; kt++) {
        if (kt + 1 < nk) fetch(kt + 1);

        const float* cA = sm + buf * 2 * TILE_F;
        const float* cB = cA + TILE_F;
#pragma unroll
        for (int e = 0; e < 2; e++) {
            float4 fa[2][2];
#pragma unroll
            for (int mi = 0; mi < 2; mi++) {
                const int R = wm * 32 + mi * 16 + r;
                fa[mi][0] = *(const float4*)&cA[R * SPITCH + cq * 8 + 4 * e];
                fa[mi][1] = *(const float4*)&cA[(R + 8) * SPITCH + cq * 8 + 4 * e];
            }
#pragma unroll
            for (int ni = 0; ni < 8; ni++) {
                const int Cn = wn * 64 + ni * 8 + r;
                float4 fb = *(const float4*)&cB[Cn * SPITCH + cq * 8 + 4 * e];
#pragma unroll
                for (int mi = 0; mi < 2; mi++) {
                    // ks = 2e
                    mma_tf32(acc[mi][ni], fa[mi][0].x, fa[mi][1].x, fa[mi][0].y, fa[mi][1].y,
                             fb.x, fb.y);
                    // ks = 2e+1
                    mma_tf32(acc[mi][ni], fa[mi][0].z, fa[mi][1].z, fa[mi][0].w, fa[mi][1].w,
                             fb.z, fb.w);
                }
            }
        }

        if (kt + 1 < nk) sts(buf ^ 1);
        __syncthreads();
        buf ^= 1;
    }

    // epilogue
#pragma unroll
    for (int ni = 0; ni < 8; ni++) {
        const int col = bn + wn * 64 + ni * 8 + cq * 2;
        const float b0 = bias[col], b1 = bias[col + 1];
#pragma unroll
        for (int mi = 0; mi < 2; mi++) {
            const int row0 = bm + wm * 32 + mi * 16 + r;
#pragma unroll
            for (int h = 0; h < 2; h++) {
                const int row = row0 + h * 8;
                float2 o;
                o.x = acc[mi][ni][h * 2 + 0] + b0;
                o.y = acc[mi][ni][h * 2 + 1] + b1;
                const size_t off = (size_t)row * N + col;
                if (EPI == 1) {
                    const float2 rr = *(const float2*)(res + off);
                    o.x += rr.x; o.y += rr.y;
                }
                if (EPI == 2) {
                    o.x = rnd_tf32(0.5f * o.x * (1.f + erff(o.x * 0.70710678118654752f)));
                    o.y = rnd_tf32(0.5f * o.y * (1.f + erff(o.y * 0.70710678118654752f)));
                }
                *(float2*)(C + off) = o;
            }
        }
    }
}

// ---------------- window attention ----------------
__global__ __launch_bounds__(256)
void win_attn_k(const float* __restrict__ qkv, const float* __restrict__ rel_table,
                const int* __restrict__ rel_idx, float* __restrict__ out)
{
    const int win = blockIdx.x;
    const int h   = blockIdx.y;
    const int b   = win >> 8;
    const int wr  = (win >> 4) & 15;
    const int wc  = win & 15;

    __shared__ float q[64][33], k[64][33], v[64][33];
    __shared__ float s[64][65];

    const int t = threadIdx.x;
#pragma unroll
    for (int i = 0; i < 8; i++) {
        int e = i * 256 + t;
        int tok = e >> 5, d = e & 31;
        int ti = tok >> 3, tj = tok & 7;
        size_t row = ((size_t)(b * 128 + wr * 8 + ti) * 128 + (wc * 8 + tj));
        const float* base = qkv + row * 768 + h * 32 + d;
        q[tok][d] = base[0];
        k[tok][d] = base[256];
        v[tok][d] = base[512];
    }
    __syncthreads();

    const int qi = t >> 2;
    const int j0 = (t & 3) * 16;
#pragma unroll
    for (int j = j0; j < j0 + 16; j++) {
        float a = 0.f;
#pragma unroll
        for (int d = 0; d < 32; d++) a = fmaf(q[qi][d], k[j][d], a);
        s[qi][j] = a * SCALE_ + rel_table[rel_idx[qi * 64 + j] * HEADS + h];
    }
    __syncthreads();

    const int warp = t >> 5, lane = t & 31;
    for (int r = warp * 8; r < warp * 8 + 8; r++) {
        float a = s[r][lane], bvv = s[r][lane + 32];
        float mx = fmaxf(a, bvv);
#pragma unroll
        for (int o = 16; o; o >>= 1) mx = fmaxf(mx, __shfl_xor_sync(0xffffffffu, mx, o));
        a = __expf(a - mx); bvv = __expf(bvv - mx);
        float sum = a + bvv;
#pragma unroll
        for (int o = 16; o; o >>= 1) sum += __shfl_xor_sync(0xffffffffu, sum, o);
        float inv = 1.f / sum;
        s[r][lane] = a * inv; s[r][lane + 32] = bvv * inv;
    }
    __syncthreads();

    const int d0 = (t & 3) * 8;
    float acc[8];
#pragma unroll
    for (int dd = 0; dd < 8; dd++) acc[dd] = 0.f;
    for (int j = 0; j < 64; j++) {
        float p = s[qi][j];
#pragma unroll
        for (int dd = 0; dd < 8; dd++) acc[dd] = fmaf(p, v[j][d0 + dd], acc[dd]);
    }
    int ti = qi >> 3, tj = qi & 7;
    size_t row = ((size_t)(b * 128 + wr * 8 + ti) * 128 + (wc * 8 + tj));
    float* ob = out + row * 256 + h * 32 + d0;
#pragma unroll
    for (int dd = 0; dd < 8; dd++) ob[dd] = acc[dd];
}

// ---------------- add + LN (ln output rounded to tf32: GEMM input only) --------
__global__ __launch_bounds__(256)
void add_ln_k(const float* __restrict__ x, const float* __restrict__ a,
              const float* __restrict__ w, const float* __restrict__ bb,
              float* __restrict__ xo, float* __restrict__ lo)
{
    const int warp = threadIdx.x >> 5, lane = threadIdx.x & 31;
    const size_t tok = (size_t)blockIdx.x * 8 + warp;
    const float* xr = x + tok * 256;
    const float* ar = a + tok * 256;
    float v[8]; float sum = 0.f;
#pragma unroll
    for (int i = 0; i < 8; i++) { int c = i * 32 + lane; v[i] = xr[c] + ar[c]; sum += v[i]; }
#pragma unroll
    for (int o = 16; o; o >>= 1) sum += __shfl_xor_sync(0xffffffffu, sum, o);
    float mean = sum * (1.f / 256.f);
    float s2 = 0.f;
#pragma unroll
    for (int i = 0; i < 8; i++) { float d = v[i] - mean; s2 += d * d; }
#pragma unroll
    for (int o = 16; o; o >>= 1) s2 += __shfl_xor_sync(0xffffffffu, s2, o);
    float rstd = rsqrtf(s2 * (1.f / 256.f) + 1e-5f);
    float* xr2 = xo + tok * 256;
    float* lr  = lo + tok * 256;
#pragma unroll
    for (int i = 0; i < 8; i++) {
        int c = i * 32 + lane;
        xr2[c] = v[i];
        lr[c]  = rnd_tf32((v[i] - mean) * rstd * w[c] + bb[c]);
    }
}

// ---------------- LN only; RND=1 rounds output (for GEMM input) ----------------
template<int RND>
__global__ __launch_bounds__(256)
void ln_k(const float* __restrict__ x, const float* __restrict__ w,
          const float* __restrict__ bb, float* __restrict__ lo)
{
    const int warp = threadIdx.x >> 5, lane = threadIdx.x & 31;
    const size_t tok = (size_t)blockIdx.x * 8 + warp;
    const float* xr = x + tok * 256;
    float v[8]; float sum = 0.f;
#pragma unroll
    for (int i = 0; i < 8; i++) { int c = i * 32 + lane; v[i] = xr[c]; sum += v[i]; }
#pragma unroll
    for (int o = 16; o; o >>= 1) sum += __shfl_xor_sync(0xffffffffu, sum, o);
    float mean = sum * (1.f / 256.f);
    float s2 = 0.f;
#pragma unroll
    for (int i = 0; i < 8; i++) { float d = v[i] - mean; s2 += d * d; }
#pragma unroll
    for (int o = 16; o; o >>= 1) s2 += __shfl_xor_sync(0xffffffffu, s2, o);
    float rstd = rsqrtf(s2 * (1.f / 256.f) + 1e-5f);
    float* lr = lo + tok * 256;
#pragma unroll
    for (int i = 0; i < 8; i++) {
        int c = i * 32 + lane;
        float o = (v[i] - mean) * rstd * w[c] + bb[c];
        lr[c] = RND ? rnd_tf32(o) : o;
    }
}

// ---------------- pool + sine pos (rounded: GEMM input only) -------------------
__global__ __launch_bounds__(256)
void pool_pos_k(const float* __restrict__ x, float* __restrict__ out)
{
    const int blk = blockIdx.x;
    const int b  = blk >> 8;
    const int ph = (blk >> 4) & 15;
    const int pw = blk & 15;
    const int c  = threadIdx.x;

    size_t base = ((size_t)(b * 128 + ph * 8) * 128 + pw * 8) * 256 + c;
    float s = 0.f;
#pragma unroll
    for (int i = 0; i < 8; i++)
#pragma unroll
        for (int j = 0; j < 8; j++)
            s += x[base + ((size_t)i * 128 + j) * 256];
    s *= (1.f / 64.f);

    float e; int cc;
    if (c < 128) { e = (float)(ph + 1); cc = c; }
    else         { e = (float)(pw + 1); cc = c - 128; }
    e = e / (16.f + 1e-5f) * 6.283185307179586f;
    float expo = (float)(cc & ~1) / 128.f;
    float tt = powf(10000.f, expo);
    float p = e / tt;
    float pe = (cc & 1) ? cosf(p) : sinf(p);
    out[(size_t)blk * 256 + c] = rnd_tf32(s + pe);
}

// ---------------- global attention ----------------
__global__ __launch_bounds__(256)
void glob_attn_k(const float* __restrict__ qkv, float* __restrict__ out)
{
    const int b = blockIdx.x >> 3;
    const int h = blockIdx.x & 7;
    __shared__ float ks[64][32], vs[64][32];

    const int t = threadIdx.x;
    float q[32];
    const float* qp = qkv + ((size_t)(b * 256 + t)) * 768 + h * 32;
#pragma unroll
    for (int d = 0; d < 32; d++) q[d] = qp[d] * SCALE_;

    float m = -1e30f, l = 0.f, acc[32];
#pragma unroll
    for (int d = 0; d < 32; d++) acc[d] = 0.f;

    for (int c0 = 0; c0 < 256; c0 += 64) {
        __syncthreads();
#pragma unroll
        for (int i = 0; i < 8; i++) {
            int e = i * 256 + t;
            int tk = e >> 5, d = e & 31;
            const float* p = qkv + ((size_t)(b * 256 + c0 + tk)) * 768 + h * 32 + d;
            ks[tk][d] = p[256];
            vs[tk][d] = p[512];
        }
        __syncthreads();
        for (int j = 0; j < 64; j++) {
            float sc = 0.f;
#pragma unroll
            for (int d = 0; d < 32; d++) sc = fmaf(q[d], ks[j][d], sc);
            float mn = fmaxf(m, sc);
            float corr = __expf(m - mn);
            float p = __expf(sc - mn);
            l = l * corr + p;
#pragma unroll
            for (int d = 0; d < 32; d++) acc[d] = acc[d] * corr + p * vs[j][d];
            m = mn;
        }
    }
    float inv = 1.f / l;
    float* op = out + ((size_t)(b * 256 + t)) * 256 + h * 32;
#pragma unroll
    for (int d = 0; d < 32; d++) op[d] = acc[d] * inv;
}

// ---------------- upsample + add + LN (ln rounded) -----------------------------
__global__ __launch_bounds__(256)
void up_add_ln_k(float* __restrict__ x, const float* __restrict__ g,
                 const float* __restrict__ w, const float* __restrict__ bb,
                 float* __restrict__ lo)
{
    const int warp = threadIdx.x >> 5, lane = threadIdx.x & 31;
    const size_t tok = (size_t)blockIdx.x * 8 + warp;
    const int b  = (int)(tok >> 14);
    const int y  = (int)((tok >> 7) & 127);
    const int xx = (int)(tok & 127);

    float sy = (float)y  * (15.f / 127.f);
    float sx = (float)xx * (15.f / 127.f);
    int y0 = (int)floorf(sy); if (y0 > 15) y0 = 15;
    int x0 = (int)floorf(sx); if (x0 > 15) x0 = 15;
    float ty = sy - (float)y0, tx = sx - (float)x0;
    int y1 = min(y0 + 1, 15), x1 = min(x0 + 1, 15);

    const float* g00 = g + ((size_t)((b * 16 + y0) * 16 + x0)) * 256;
    const float* g01 = g + ((size_t)((b * 16 + y0) * 16 + x1)) * 256;
    const float* g10 = g + ((size_t)((b * 16 + y1) * 16 + x0)) * 256;
    const float* g11 = g + ((size_t)((b * 16 + y1) * 16 + x1)) * 256;
    float w00 = (1.f - ty) * (1.f - tx), w01 = (1.f - ty) * tx;
    float w10 = ty * (1.f - tx),         w11 = ty * tx;

    float* xr = x + tok * 256;
    float v[8]; float sum = 0.f;
#pragma unroll
    for (int i = 0; i < 8; i++) {
        int c = i * 32 + lane;
        float up = g00[c] * w00 + g01[c] * w01 + g10[c] * w10 + g11[c] * w11;
        v[i] = xr[c] + up;
        sum += v[i];
    }
#pragma unroll
    for (int o = 16; o; o >>= 1) sum += __shfl_xor_sync(0xffffffffu, sum, o);
    float mean = sum * (1.f / 256.f);
    float s2 = 0.f;
#pragma unroll
    for (int i = 0; i < 8; i++) { float d = v[i] - mean; s2 += d * d; }
#pragma unroll
    for (int o = 16; o; o >>= 1) s2 += __shfl_xor_sync(0xffffffffu, s2, o);
    float rstd = rsqrtf(s2 * (1.f / 256.f) + 1e-5f);
    float* lr = lo + tok * 256;
#pragma unroll
    for (int i = 0; i < 8; i++) {
        int c = i * 32 + lane;
        xr[c] = v[i];
        lr[c] = rnd_tf32((v[i] - mean) * rstd * w[c] + bb[c]);
    }
}

// ---------------- launch ----------------
static float* symaddr(const void* sym)
{
    void* p = nullptr;
    cudaGetSymbolAddress(&p, sym);
    return (float*)p;
}
static void round_arr(const float* in, float* out, int n)
{
    int n4 = n / 4;
    round4_k<<<(n4 + 255) / 256, 256>>>((const float4*)in, (float4*)out, n4);
}

extern "C" void kernel_launch(void* const* d_in, const int* in_sizes, int n_in,
                              void* d_out, int out_size)
{
    const float* x          = (const float*)d_in[0];
    const float* rel_table  = (const float*)d_in[1];
    const float* qkv_w      = (const float*)d_in[2];
    const float* qkv_b      = (const float*)d_in[3];
    const float* qkv2_w     = (const float*)d_in[4];
    const float* qkv2_b     = (const float*)d_in[5];
    const float* proj_ln_w  = (const float*)d_in[6];
    const float* proj_ln_b  = (const float*)d_in[7];
    const float* proj_w     = (const float*)d_in[8];
    const float* proj_b     = (const float*)d_in[9];
    const float* proj2_ln_w = (const float*)d_in[10];
    const float* proj2_ln_b = (const float*)d_in[11];
    const float* proj2_w    = (const float*)d_in[12];
    const float* proj2_b    = (const float*)d_in[13];
    const float* norm1_w    = (const float*)d_in[14];
    const float* norm1_b    = (const float*)d_in[15];
    const float* norm2_w    = (const float*)d_in[16];
    const float* norm2_b    = (const float*)d_in[17];
    const float* fc1_w      = (const float*)d_in[18];
    const float* fc1_b      = (const float*)d_in[19];
    const float* fc2_w      = (const float*)d_in[20];
    const float* fc2_b      = (const float*)d_in[21];
    const int*   rel_idx    = (const int*)  d_in[22];

    float* qkv   = symaddr(g_qkv);
    float* attn  = symaddr(g_attn);
    float* xb    = symaddr(g_x);
    float* ln    = symaddr(g_ln);
    float* hbuf  = symaddr(g_h);
    float* pool  = symaddr(g_pool);
    float* qkvg  = symaddr(g_qkvg);
    float* attng = symaddr(g_attng);
    float* wr    = symaddr(g_wr);

    cudaFuncSetAttribute(mgemm_k<0>, cudaFuncAttributeMaxDynamicSharedMemorySize, MGEMM_SMEM);
    cudaFuncSetAttribute(mgemm_k<1>, cudaFuncAttributeMaxDynamicSharedMemorySize, MGEMM_SMEM);
    cudaFuncSetAttribute(mgemm_k<2>, cudaFuncAttributeMaxDynamicSharedMemorySize, MGEMM_SMEM);

    const int M = NTOK;

    // 0) pre-round weights + input x to tf32 (rna)
    round_arr(qkv_w,   wr + OFF_QKVW,  768 * 256);
    round_arr(proj_w,  wr + OFF_PROJW, 256 * 256);
    round_arr(proj2_w, wr + OFF_PROJ2W,256 * 256);
    round_arr(fc1_w,   wr + OFF_FC1W,  1024 * 256);
    round_arr(fc2_w,   wr + OFF_FC2W,  256 * 1024);
    round_arr(qkv2_w,  wr + OFF_QKV2W, 768 * 256);
    round_arr(x, attn, M * 256);    // attn buffer reused as rounded x

    // 1) window-branch QKV (tf32 mma.sync, pre-rounded operands)
    mgemm_k<0><<<dim3(M/128, 6), 256, MGEMM_SMEM>>>(attn, wr + OFF_QKVW, qkv_b, nullptr, qkv, M, 768, 256);
    // 2) window attention
    win_attn_k<<<dim3(2048, 8), 256>>>(qkv, rel_table, rel_idx, attn);
    // 3) x = x + attn ; ln = LN(x) (rounded)
    add_ln_k<<<M/8, 256>>>(x, attn, proj_ln_w, proj_ln_b, xb, ln);
    // 4) x += ln @ proj_w^T + proj_b
    mgemm_k<1><<<dim3(M/128, 2), 256, MGEMM_SMEM>>>(ln, wr + OFF_PROJW, proj_b, xb, xb, M, 256, 256);
    // 5) pool + sine pos (rounded)
    pool_pos_k<<<2048, 256>>>(xb, pool);
    // 6) global QKV
    mgemm_k<0><<<dim3(16, 6), 256, MGEMM_SMEM>>>(pool, wr + OFF_QKV2W, qkv2_b, nullptr, qkvg, 2048, 768, 256);
    // 7) global attention
    glob_attn_k<<<64, 256>>>(qkvg, attng);
    // 8) x += upsample(attng) ; ln = LN(x) (rounded)
    up_add_ln_k<<<M/8, 256>>>(xb, attng, proj2_ln_w, proj2_ln_b, ln);
    // 9) x += ln @ proj2_w^T + proj2_b
    mgemm_k<1><<<dim3(M/128, 2), 256, MGEMM_SMEM>>>(ln, wr + OFF_PROJ2W, proj2_b, xb, xb, M, 256, 256);
    // 10) ln = LN(x, norm1) (rounded)
    ln_k<1><<<M/8, 256>>>(xb, norm1_w, norm1_b, ln);
    // 11) h = gelu(ln @ fc1^T) (rounded output)
    mgemm_k<2><<<dim3(M/128, 8), 256, MGEMM_SMEM>>>(ln, wr + OFF_FC1W, fc1_b, nullptr, hbuf, M, 1024, 256);
    // 12) x += h @ fc2^T
    mgemm_k<1><<<dim3(M/128, 2), 256, MGEMM_SMEM>>>(hbuf, wr + OFF_FC2W, fc2_b, xb, xb, M, 256, 1024);
    // 13) out = LN(x, norm2) (exact)
    ln_k<0><<<M/8, 256>>>(xb, norm2_w, norm2_b, (float*)d_out);
}

// round 5
// speedup vs baseline: 1.5139x; 1.5139x over previous
#include <cuda_runtime.h>
#include <cuda_bf16.h>
#include <math.h>
#include <stdint.h>

#define DIM 256
#define HEADS 8
#define WS 8
#define B_ 8
#define NTOK (B_*128*128)          // 131072
#define MLP_HIDDEN 1024
#define SCALE_ 0.17677669529663687f

// ---------------- scratch ----------------
__device__ float g_qkv [NTOK * 768];
__device__ float g_attn[NTOK * DIM];          // reused as rounded-x before step 2
__device__ float g_x   [NTOK * DIM];
__device__ float g_ln  [NTOK * DIM];
__device__ float g_h   [NTOK * MLP_HIDDEN];
__device__ float g_pool [B_ * 256 * DIM];
__device__ float g_qkvg [B_ * 256 * 768];
__device__ float g_attng[B_ * 256 * DIM];
__device__ float g_wr  [1048576];             // rounded weights

#define OFF_QKVW  0
#define OFF_PROJW 196608
#define OFF_PROJ2W 262144
#define OFF_FC1W  327680
#define OFF_FC2W  589824
#define OFF_QKV2W 851968

// ---------------- helpers ----------------
__device__ __forceinline__ uint32_t smem_u32(const void* p) {
    uint32_t a;
    asm("{ .reg .u64 t; cvta.to.shared.u64 t, %1; cvt.u32.u64 %0, t; }" : "=r"(a) : "l"(p));
    return a;
}
#define CP16(dst, src) \
    asm volatile("cp.async.cg.shared.global [%0], [%1], 16;" :: "r"(dst), "l"(src))
#define CP_COMMIT() asm volatile("cp.async.commit_group;" ::: "memory")
#define CP_WAIT1()  asm volatile("cp.async.wait_group 1;" ::: "memory")

__device__ __forceinline__ uint32_t f2tf32(float f) {
    uint32_t u;
    asm("cvt.rna.tf32.f32 %0, %1;" : "=r"(u) : "f"(f));
    return u;
}
__device__ __forceinline__ float rnd_tf32(float f) {
    return __uint_as_float(f2tf32(f));
}
// operands already tf32-valued; bit-cast straight into HMMA
__device__ __forceinline__ void mma_tf32(float* d, float a0, float a1, float a2, float a3,
                                         float b0, float b1) {
    asm volatile(
        "mma.sync.aligned.m16n8k8.row.col.f32.tf32.tf32.f32 "
        "{%0,%1,%2,%3}, {%4,%5,%6,%7}, {%8,%9}, {%0,%1,%2,%3};"
        : "+f"(d[0]), "+f"(d[1]), "+f"(d[2]), "+f"(d[3])
        : "r"(__float_as_uint(a0)), "r"(__float_as_uint(a1)),
          "r"(__float_as_uint(a2)), "r"(__float_as_uint(a3)),
          "r"(__float_as_uint(b0)), "r"(__float_as_uint(b1)));
}

// ---------------- tf32 round kernel ----------------
__global__ __launch_bounds__(256)
void round4_k(const float4* __restrict__ in, float4* __restrict__ out, int n4)
{
    int i = blockIdx.x * 256 + threadIdx.x;
    if (i < n4) {
        float4 v = in[i];
        v.x = rnd_tf32(v.x); v.y = rnd_tf32(v.y);
        v.z = rnd_tf32(v.z); v.w = rnd_tf32(v.w);
        out[i] = v;
    }
}

// ---------------- tf32 mma.sync GEMM (R3 pipeline, pre-rounded operands) -------
// C[M,N] = A[M,K] @ B[N,K]^T + bias (+epi)
// EPI: 0 none, 1 +res, 2 gelu(exact, rounded output)
#define BM 128
#define BN 128
#define BK 32
#define STG 3
#define APAD 36
#define ASZ (BM*APAD)
#define BSZ (BN*APAD)
#define STAGE_F (ASZ + BSZ)
#define MGEMM_SMEM (STG * STAGE_F * 4)

__device__ __forceinline__ void load_tile(const float* __restrict__ Ag,
                                          const float* __restrict__ Bg,
                                          int K, uint32_t sA, uint32_t sB, int t)
{
#pragma unroll
    for (int i = 0; i < 4; i++) {
        int idx = i * 256 + t;
        int row = idx >> 3, ch = idx & 7;
        CP16(sA + row * (APAD * 4) + ch * 16, Ag + (size_t)row * K + ch * 4);
    }
#pragma unroll
    for (int i = 0; i < 4; i++) {
        int idx = i * 256 + t;
        int row = idx >> 3, ch = idx & 7;
        CP16(sB + row * (APAD * 4) + ch * 16, Bg + (size_t)row * K + ch * 4);
    }
}

template<int EPI>
__global__ __launch_bounds__(256)
void mgemm_k(const float* __restrict__ A, const float* __restrict__ Bw,
             const float* __restrict__ bias, const float* __restrict__ res,
             float* __restrict__ C, int M, int N, int K)
{
    extern __shared__ float sm[];
    const uint32_t smb = smem_u32(sm);

    const int t = threadIdx.x, lane = t & 31, warp = t >> 5;
    const int wm = warp >> 1, wn = warp & 1;
    const int bm = blockIdx.x * BM, bn = blockIdx.y * BN;
    const int nk = K / BK;
    const int r = lane >> 2, cq = lane & 3;

    float acc[2][8][4];
#pragma unroll
    for (int i = 0; i < 2; i++)
#pragma unroll
        for (int j = 0; j < 8; j++)
#pragma unroll
            for (int q = 0; q < 4; q++) acc[i][j][q] = 0.f;

    const float* Abase = A + (size_t)bm * K;
    const float* Bbase = Bw + (size_t)bn * K;

#pragma unroll
    for (int s = 0; s < STG - 1; s++) {
        load_tile(Abase + s * BK, Bbase + s * BK, K,
                  smb + s * STAGE_F * 4, smb + (s * STAGE_F + ASZ) * 4, t);
        CP_COMMIT();
    }

    for (int kt = 0; kt < nk; kt++) {
        CP_WAIT1();
        __syncthreads();
        const int pf = kt + STG - 1;
        if (pf < nk) {
            const int st = pf % STG;
            load_tile(Abase + pf * BK, Bbase + pf * BK, K,
                      smb + st * STAGE_F * 4, smb + (st * STAGE_F + ASZ) * 4, t);
        }
        CP_COMMIT();

        const float* sA = sm + (kt % STG) * STAGE_F;
        const float* sB = sA + ASZ;
#pragma unroll
        for (int ks = 0; ks < 4; ks++) {
            const int k0 = ks * 8;
            float a[2][4];
#pragma unroll
            for (int mi = 0; mi < 2; mi++) {
                const int row = wm * 32 + mi * 16;
                a[mi][0] = sA[(row + r)     * APAD + k0 + cq];
                a[mi][1] = sA[(row + r + 8) * APAD + k0 + cq];
                a[mi][2] = sA[(row + r)     * APAD + k0 + cq + 4];
                a[mi][3] = sA[(row + r + 8) * APAD + k0 + cq + 4];
            }
            float b[8][2];
#pragma unroll
            for (int ni = 0; ni < 8; ni++) {
                const int col = wn * 64 + ni * 8;
                b[ni][0] = sB[(col + r) * APAD + k0 + cq];
                b[ni][1] = sB[(col + r) * APAD + k0 + cq + 4];
            }
#pragma unroll
            for (int mi = 0; mi < 2; mi++)
#pragma unroll
                for (int ni = 0; ni < 8; ni++)
                    mma_tf32(acc[mi][ni], a[mi][0], a[mi][1], a[mi][2], a[mi][3],
                             b[ni][0], b[ni][1]);
        }
    }

    // epilogue
#pragma unroll
    for (int ni = 0; ni < 8; ni++) {
        const int col = bn + wn * 64 + ni * 8 + cq * 2;
        const float b0 = bias[col], b1 = bias[col + 1];
#pragma unroll
        for (int mi = 0; mi < 2; mi++) {
            const int row0 = bm + wm * 32 + mi * 16 + r;
#pragma unroll
            for (int h = 0; h < 2; h++) {
                const int row = row0 + h * 8;
                float2 o;
                o.x = acc[mi][ni][h * 2 + 0] + b0;
                o.y = acc[mi][ni][h * 2 + 1] + b1;
                const size_t off = (size_t)row * N + col;
                if (EPI == 1) {
                    const float2 rr = *(const float2*)(res + off);
                    o.x += rr.x; o.y += rr.y;
                }
                if (EPI == 2) {
                    o.x = rnd_tf32(0.5f * o.x * (1.f + erff(o.x * 0.70710678118654752f)));
                    o.y = rnd_tf32(0.5f * o.y * (1.f + erff(o.y * 0.70710678118654752f)));
                }
                *(float2*)(C + off) = o;
            }
        }
    }
}

// ---------------- window attention ----------------
__global__ __launch_bounds__(256)
void win_attn_k(const float* __restrict__ qkv, const float* __restrict__ rel_table,
                const int* __restrict__ rel_idx, float* __restrict__ out)
{
    const int win = blockIdx.x;
    const int h   = blockIdx.y;
    const int b   = win >> 8;
    const int wr  = (win >> 4) & 15;
    const int wc  = win & 15;

    __shared__ float q[64][33], k[64][33], v[64][33];
    __shared__ float s[64][65];

    const int t = threadIdx.x;
#pragma unroll
    for (int i = 0; i < 8; i++) {
        int e = i * 256 + t;
        int tok = e >> 5, d = e & 31;
        int ti = tok >> 3, tj = tok & 7;
        size_t row = ((size_t)(b * 128 + wr * 8 + ti) * 128 + (wc * 8 + tj));
        const float* base = qkv + row * 768 + h * 32 + d;
        q[tok][d] = base[0];
        k[tok][d] = base[256];
        v[tok][d] = base[512];
    }
    __syncthreads();

    const int qi = t >> 2;
    const int j0 = (t & 3) * 16;
#pragma unroll
    for (int j = j0; j < j0 + 16; j++) {
        float a = 0.f;
#pragma unroll
        for (int d = 0; d < 32; d++) a = fmaf(q[qi][d], k[j][d], a);
        s[qi][j] = a * SCALE_ + rel_table[rel_idx[qi * 64 + j] * HEADS + h];
    }
    __syncthreads();

    const int warp = t >> 5, lane = t & 31;
    for (int r = warp * 8; r < warp * 8 + 8; r++) {
        float a = s[r][lane], bvv = s[r][lane + 32];
        float mx = fmaxf(a, bvv);
#pragma unroll
        for (int o = 16; o; o >>= 1) mx = fmaxf(mx, __shfl_xor_sync(0xffffffffu, mx, o));
        a = __expf(a - mx); bvv = __expf(bvv - mx);
        float sum = a + bvv;
#pragma unroll
        for (int o = 16; o; o >>= 1) sum += __shfl_xor_sync(0xffffffffu, sum, o);
        float inv = 1.f / sum;
        s[r][lane] = a * inv; s[r][lane + 32] = bvv * inv;
    }
    __syncthreads();

    const int d0 = (t & 3) * 8;
    float acc[8];
#pragma unroll
    for (int dd = 0; dd < 8; dd++) acc[dd] = 0.f;
    for (int j = 0; j < 64; j++) {
        float p = s[qi][j];
#pragma unroll
        for (int dd = 0; dd < 8; dd++) acc[dd] = fmaf(p, v[j][d0 + dd], acc[dd]);
    }
    int ti = qi >> 3, tj = qi & 7;
    size_t row = ((size_t)(b * 128 + wr * 8 + ti) * 128 + (wc * 8 + tj));
    float* ob = out + row * 256 + h * 32 + d0;
#pragma unroll
    for (int dd = 0; dd < 8; dd++) ob[dd] = acc[dd];
}

// ---------------- add + LN (ln rounded) ----------------
__global__ __launch_bounds__(256)
void add_ln_k(const float* __restrict__ x, const float* __restrict__ a,
              const float* __restrict__ w, const float* __restrict__ bb,
              float* __restrict__ xo, float* __restrict__ lo)
{
    const int warp = threadIdx.x >> 5, lane = threadIdx.x & 31;
    const size_t tok = (size_t)blockIdx.x * 8 + warp;
    const float* xr = x + tok * 256;
    const float* ar = a + tok * 256;
    float v[8]; float sum = 0.f;
#pragma unroll
    for (int i = 0; i < 8; i++) { int c = i * 32 + lane; v[i] = xr[c] + ar[c]; sum += v[i]; }
#pragma unroll
    for (int o = 16; o; o >>= 1) sum += __shfl_xor_sync(0xffffffffu, sum, o);
    float mean = sum * (1.f / 256.f);
    float s2 = 0.f;
#pragma unroll
    for (int i = 0; i < 8; i++) { float d = v[i] - mean; s2 += d * d; }
#pragma unroll
    for (int o = 16; o; o >>= 1) s2 += __shfl_xor_sync(0xffffffffu, s2, o);
    float rstd = rsqrtf(s2 * (1.f / 256.f) + 1e-5f);
    float* xr2 = xo + tok * 256;
    float* lr  = lo + tok * 256;
#pragma unroll
    for (int i = 0; i < 8; i++) {
        int c = i * 32 + lane;
        xr2[c] = v[i];
        lr[c]  = rnd_tf32((v[i] - mean) * rstd * w[c] + bb[c]);
    }
}

// ---------------- LN only ----------------
template<int RND>
__global__ __launch_bounds__(256)
void ln_k(const float* __restrict__ x, const float* __restrict__ w,
          const float* __restrict__ bb, float* __restrict__ lo)
{
    const int warp = threadIdx.x >> 5, lane = threadIdx.x & 31;
    const size_t tok = (size_t)blockIdx.x * 8 + warp;
    const float* xr = x + tok * 256;
    float v[8]; float sum = 0.f;
#pragma unroll
    for (int i = 0; i < 8; i++) { int c = i * 32 + lane; v[i] = xr[c]; sum += v[i]; }
#pragma unroll
    for (int o = 16; o; o >>= 1) sum += __shfl_xor_sync(0xffffffffu, sum, o);
    float mean = sum * (1.f / 256.f);
    float s2 = 0.f;
#pragma unroll
    for (int i = 0; i < 8; i++) { float d = v[i] - mean; s2 += d * d; }
#pragma unroll
    for (int o = 16; o; o >>= 1) s2 += __shfl_xor_sync(0xffffffffu, s2, o);
    float rstd = rsqrtf(s2 * (1.f / 256.f) + 1e-5f);
    float* lr = lo + tok * 256;
#pragma unroll
    for (int i = 0; i < 8; i++) {
        int c = i * 32 + lane;
        float o = (v[i] - mean) * rstd * w[c] + bb[c];
        lr[c] = RND ? rnd_tf32(o) : o;
    }
}

// ---------------- pool + sine pos (rounded) ----------------
__global__ __launch_bounds__(256)
void pool_pos_k(const float* __restrict__ x, float* __restrict__ out)
{
    const int blk = blockIdx.x;
    const int b  = blk >> 8;
    const int ph = (blk >> 4) & 15;
    const int pw = blk & 15;
    const int c  = threadIdx.x;

    size_t base = ((size_t)(b * 128 + ph * 8) * 128 + pw * 8) * 256 + c;
    float s = 0.f;
#pragma unroll
    for (int i = 0; i < 8; i++)
#pragma unroll
        for (int j = 0; j < 8; j++)
            s += x[base + ((size_t)i * 128 + j) * 256];
    s *= (1.f / 64.f);

    float e; int cc;
    if (c < 128) { e = (float)(ph + 1); cc = c; }
    else         { e = (float)(pw + 1); cc = c - 128; }
    e = e / (16.f + 1e-5f) * 6.283185307179586f;
    float expo = (float)(cc & ~1) / 128.f;
    float tt = powf(10000.f, expo);
    float p = e / tt;
    float pe = (cc & 1) ? cosf(p) : sinf(p);
    out[(size_t)blk * 256 + c] = rnd_tf32(s + pe);
}

// ---------------- global attention ----------------
__global__ __launch_bounds__(256)
void glob_attn_k(const float* __restrict__ qkv, float* __restrict__ out)
{
    const int b = blockIdx.x >> 3;
    const int h = blockIdx.x & 7;
    __shared__ float ks[64][32], vs[64][32];

    const int t = threadIdx.x;
    float q[32];
    const float* qp = qkv + ((size_t)(b * 256 + t)) * 768 + h * 32;
#pragma unroll
    for (int d = 0; d < 32; d++) q[d] = qp[d] * SCALE_;

    float m = -1e30f, l = 0.f, acc[32];
#pragma unroll
    for (int d = 0; d < 32; d++) acc[d] = 0.f;

    for (int c0 = 0; c0 < 256; c0 += 64) {
        __syncthreads();
#pragma unroll
        for (int i = 0; i < 8; i++) {
            int e = i * 256 + t;
            int tk = e >> 5, d = e & 31;
            const float* p = qkv + ((size_t)(b * 256 + c0 + tk)) * 768 + h * 32 + d;
            ks[tk][d] = p[256];
            vs[tk][d] = p[512];
        }
        __syncthreads();
        for (int j = 0; j < 64; j++) {
            float sc = 0.f;
#pragma unroll
            for (int d = 0; d < 32; d++) sc = fmaf(q[d], ks[j][d], sc);
            float mn = fmaxf(m, sc);
            float corr = __expf(m - mn);
            float p = __expf(sc - mn);
            l = l * corr + p;
#pragma unroll
            for (int d = 0; d < 32; d++) acc[d] = acc[d] * corr + p * vs[j][d];
            m = mn;
        }
    }
    float inv = 1.f / l;
    float* op = out + ((size_t)(b * 256 + t)) * 256 + h * 32;
#pragma unroll
    for (int d = 0; d < 32; d++) op[d] = acc[d] * inv;
}

// ---------------- upsample + add + LN (ln rounded) ----------------
__global__ __launch_bounds__(256)
void up_add_ln_k(float* __restrict__ x, const float* __restrict__ g,
                 const float* __restrict__ w, const float* __restrict__ bb,
                 float* __restrict__ lo)
{
    const int warp = threadIdx.x >> 5, lane = threadIdx.x & 31;
    const size_t tok = (size_t)blockIdx.x * 8 + warp;
    const int b  = (int)(tok >> 14);
    const int y  = (int)((tok >> 7) & 127);
    const int xx = (int)(tok & 127);

    float sy = (float)y  * (15.f / 127.f);
    float sx = (float)xx * (15.f / 127.f);
    int y0 = (int)floorf(sy); if (y0 > 15) y0 = 15;
    int x0 = (int)floorf(sx); if (x0 > 15) x0 = 15;
    float ty = sy - (float)y0, tx = sx - (float)x0;
    int y1 = min(y0 + 1, 15), x1 = min(x0 + 1, 15);

    const float* g00 = g + ((size_t)((b * 16 + y0) * 16 + x0)) * 256;
    const float* g01 = g + ((size_t)((b * 16 + y0) * 16 + x1)) * 256;
    const float* g10 = g + ((size_t)((b * 16 + y1) * 16 + x0)) * 256;
    const float* g11 = g + ((size_t)((b * 16 + y1) * 16 + x1)) * 256;
    float w00 = (1.f - ty) * (1.f - tx), w01 = (1.f - ty) * tx;
    float w10 = ty * (1.f - tx),         w11 = ty * tx;

    float* xr = x + tok * 256;
    float v[8]; float sum = 0.f;
#pragma unroll
    for (int i = 0; i < 8; i++) {
        int c = i * 32 + lane;
        float up = g00[c] * w00 + g01[c] * w01 + g10[c] * w10 + g11[c] * w11;
        v[i] = xr[c] + up;
        sum += v[i];
    }
#pragma unroll
    for (int o = 16; o; o >>= 1) sum += __shfl_xor_sync(0xffffffffu, sum, o);
    float mean = sum * (1.f / 256.f);
    float s2 = 0.f;
#pragma unroll
    for (int i = 0; i < 8; i++) { float d = v[i] - mean; s2 += d * d; }
#pragma unroll
    for (int o = 16; o; o >>= 1) s2 += __shfl_xor_sync(0xffffffffu, s2, o);
    float rstd = rsqrtf(s2 * (1.f / 256.f) + 1e-5f);
    float* lr = lo + tok * 256;
#pragma unroll
    for (int i = 0; i < 8; i++) {
        int c = i * 32 + lane;
        xr[c] = v[i];
        lr[c] = rnd_tf32((v[i] - mean) * rstd * w[c] + bb[c]);
    }
}

// ---------------- launch ----------------
static float* symaddr(const void* sym)
{
    void* p = nullptr;
    cudaGetSymbolAddress(&p, sym);
    return (float*)p;
}
static void round_arr(const float* in, float* out, int n)
{
    int n4 = n / 4;
    round4_k<<<(n4 + 255) / 256, 256>>>((const float4*)in, (float4*)out, n4);
}

extern "C" void kernel_launch(void* const* d_in, const int* in_sizes, int n_in,
                              void* d_out, int out_size)
{
    const float* x          = (const float*)d_in[0];
    const float* rel_table  = (const float*)d_in[1];
    const float* qkv_w      = (const float*)d_in[2];
    const float* qkv_b      = (const float*)d_in[3];
    const float* qkv2_w     = (const float*)d_in[4];
    const float* qkv2_b     = (const float*)d_in[5];
    const float* proj_ln_w  = (const float*)d_in[6];
    const float* proj_ln_b  = (const float*)d_in[7];
    const float* proj_w     = (const float*)d_in[8];
    const float* proj_b     = (const float*)d_in[9];
    const float* proj2_ln_w = (const float*)d_in[10];
    const float* proj2_ln_b = (const float*)d_in[11];
    const float* proj2_w    = (const float*)d_in[12];
    const float* proj2_b    = (const float*)d_in[13];
    const float* norm1_w    = (const float*)d_in[14];
    const float* norm1_b    = (const float*)d_in[15];
    const float* norm2_w    = (const float*)d_in[16];
    const float* norm2_b    = (const float*)d_in[17];
    const float* fc1_w      = (const float*)d_in[18];
    const float* fc1_b      = (const float*)d_in[19];
    const float* fc2_w      = (const float*)d_in[20];
    const float* fc2_b      = (const float*)d_in[21];
    const int*   rel_idx    = (const int*)  d_in[22];

    float* qkv   = symaddr(g_qkv);
    float* attn  = symaddr(g_attn);
    float* xb    = symaddr(g_x);
    float* ln    = symaddr(g_ln);
    float* hbuf  = symaddr(g_h);
    float* pool  = symaddr(g_pool);
    float* qkvg  = symaddr(g_qkvg);
    float* attng = symaddr(g_attng);
    float* wr    = symaddr(g_wr);

    cudaFuncSetAttribute(mgemm_k<0>, cudaFuncAttributeMaxDynamicSharedMemorySize, MGEMM_SMEM);
    cudaFuncSetAttribute(mgemm_k<1>, cudaFuncAttributeMaxDynamicSharedMemorySize, MGEMM_SMEM);
    cudaFuncSetAttribute(mgemm_k<2>, cudaFuncAttributeMaxDynamicSharedMemorySize, MGEMM_SMEM);

    const int M = NTOK;

    // 0) pre-round weights + input x to tf32 (rna)
    round_arr(qkv_w,   wr + OFF_QKVW,  768 * 256);
    round_arr(proj_w,  wr + OFF_PROJW, 256 * 256);
    round_arr(proj2_w, wr + OFF_PROJ2W,256 * 256);
    round_arr(fc1_w,   wr + OFF_FC1W,  1024 * 256);
    round_arr(fc2_w,   wr + OFF_FC2W,  256 * 1024);
    round_arr(qkv2_w,  wr + OFF_QKV2W, 768 * 256);
    round_arr(x, attn, M * 256);

    // 1) window-branch QKV
    mgemm_k<0><<<dim3(M/128, 6), 256, MGEMM_SMEM>>>(attn, wr + OFF_QKVW, qkv_b, nullptr, qkv, M, 768, 256);
    // 2) window attention
    win_attn_k<<<dim3(2048, 8), 256>>>(qkv, rel_table, rel_idx, attn);
    // 3) x = x + attn ; ln = LN(x)
    add_ln_k<<<M/8, 256>>>(x, attn, proj_ln_w, proj_ln_b, xb, ln);
    // 4) x += ln @ proj_w^T + proj_b
    mgemm_k<1><<<dim3(M/128, 2), 256, MGEMM_SMEM>>>(ln, wr + OFF_PROJW, proj_b, xb, xb, M, 256, 256);
    // 5) pool + sine pos
    pool_pos_k<<<2048, 256>>>(xb, pool);
    // 6) global QKV
    mgemm_k<0><<<dim3(16, 6), 256, MGEMM_SMEM>>>(pool, wr + OFF_QKV2W, qkv2_b, nullptr, qkvg, 2048, 768, 256);
    // 7) global attention
    glob_attn_k<<<64, 256>>>(qkvg, attng);
    // 8) x += upsample(attng) ; ln = LN(x)
    up_add_ln_k<<<M/8, 256>>>(xb, attng, proj2_ln_w, proj2_ln_b, ln);
    // 9) x += ln @ proj2_w^T + proj2_b
    mgemm_k<1><<<dim3(M/128, 2), 256, MGEMM_SMEM>>>(ln, wr + OFF_PROJ2W, proj2_b, xb, xb, M, 256, 256);
    // 10) ln = LN(x, norm1)
    ln_k<1><<<M/8, 256>>>(xb, norm1_w, norm1_b, ln);
    // 11) h = gelu(ln @ fc1^T)
    mgemm_k<2><<<dim3(M/128, 8), 256, MGEMM_SMEM>>>(ln, wr + OFF_FC1W, fc1_b, nullptr, hbuf, M, 1024, 256);
    // 12) x += h @ fc2^T
    mgemm_k<1><<<dim3(M/128, 2), 256, MGEMM_SMEM>>>(hbuf, wr + OFF_FC2W, fc2_b, xb, xb, M, 256, 1024);
    // 13) out = LN(x, norm2)
    ln_k<0><<<M/8, 256>>>(xb, norm2_w, norm2_b, (float*)d_out);
}

// round 6
// speedup vs baseline: 1.5166x; 1.0018x over previous
#include <cuda_runtime.h>
#include <cuda_bf16.h>
#include <math.h>
#include <stdint.h>

#define DIM 256
#define HEADS 8
#define WS 8
#define B_ 8
#define NTOK (B_*128*128)          // 131072
#define MLP_HIDDEN 1024
#define SCALE_ 0.17677669529663687f

// ---------------- scratch ----------------
__device__ float g_qkv [NTOK * 768];
__device__ float g_attn[NTOK * DIM];          // reused as rounded-x before step 2
__device__ float g_x   [NTOK * DIM];
__device__ float g_ln  [NTOK * DIM];
__device__ float g_h   [NTOK * MLP_HIDDEN];
__device__ float g_pool [B_ * 256 * DIM];
__device__ float g_qkvg [B_ * 256 * 768];
__device__ float g_attng[B_ * 256 * DIM];
__device__ float g_wr  [1048576];             // rounded weights

#define OFF_QKVW  0
#define OFF_PROJW 196608
#define OFF_PROJ2W 262144
#define OFF_FC1W  327680
#define OFF_FC2W  589824
#define OFF_QKV2W 851968

// ---------------- helpers ----------------
__device__ __forceinline__ uint32_t smem_u32(const void* p) {
    uint32_t a;
    asm("{ .reg .u64 t; cvta.to.shared.u64 t, %1; cvt.u32.u64 %0, t; }" : "=r"(a) : "l"(p));
    return a;
}
#define CP16(dst, src) \
    asm volatile("cp.async.cg.shared.global [%0], [%1], 16;" :: "r"(dst), "l"(src))
#define CP_COMMIT() asm volatile("cp.async.commit_group;" ::: "memory")
#define CP_WAIT1()  asm volatile("cp.async.wait_group 1;" ::: "memory")

__device__ __forceinline__ uint32_t f2tf32(float f) {
    uint32_t u;
    asm("cvt.rna.tf32.f32 %0, %1;" : "=r"(u) : "f"(f));
    return u;
}
__device__ __forceinline__ float rnd_tf32(float f) {
    return __uint_as_float(f2tf32(f));
}
// operands already tf32-valued; bit-cast straight into HMMA
__device__ __forceinline__ void mma_tf32(float* d, float a0, float a1, float a2, float a3,
                                         float b0, float b1) {
    asm volatile(
        "mma.sync.aligned.m16n8k8.row.col.f32.tf32.tf32.f32 "
        "{%0,%1,%2,%3}, {%4,%5,%6,%7}, {%8,%9}, {%0,%1,%2,%3};"
        : "+f"(d[0]), "+f"(d[1]), "+f"(d[2]), "+f"(d[3])
        : "r"(__float_as_uint(a0)), "r"(__float_as_uint(a1)),
          "r"(__float_as_uint(a2)), "r"(__float_as_uint(a3)),
          "r"(__float_as_uint(b0)), "r"(__float_as_uint(b1)));
}

// ---------------- tf32 round kernel ----------------
__global__ __launch_bounds__(256)
void round4_k(const float4* __restrict__ in, float4* __restrict__ out, int n4)
{
    int i = blockIdx.x * 256 + threadIdx.x;
    if (i < n4) {
        float4 v = in[i];
        v.x = rnd_tf32(v.x); v.y = rnd_tf32(v.y);
        v.z = rnd_tf32(v.z); v.w = rnd_tf32(v.w);
        out[i] = v;
    }
}

// ---------------- tf32 mma.sync GEMM (2 CTAs/SM) --------------------------------
// C[M,N] = A[M,K] @ B[N,K]^T + bias (+epi); A,B pre-rounded to tf32
// EPI: 0 none, 1 +res, 2 gelu(exact, rounded output)
#define BM 128
#define BN 128
#define BK 32
#define STG 3
#define APAD 36
#define ASZ (BM*APAD)
#define BSZ (BN*APAD)
#define STAGE_F (ASZ + BSZ)
#define MGEMM_SMEM (STG * STAGE_F * 4)   // 110592 B; 2 per SM = 221184 <= 228KB

__device__ __forceinline__ void load_tile(const float* __restrict__ Ag,
                                          const float* __restrict__ Bg,
                                          int K, uint32_t sA, uint32_t sB, int t)
{
#pragma unroll
    for (int i = 0; i < 4; i++) {
        int idx = i * 256 + t;
        int row = idx >> 3, ch = idx & 7;
        CP16(sA + row * (APAD * 4) + ch * 16, Ag + (size_t)row * K + ch * 4);
    }
#pragma unroll
    for (int i = 0; i < 4; i++) {
        int idx = i * 256 + t;
        int row = idx >> 3, ch = idx & 7;
        CP16(sB + row * (APAD * 4) + ch * 16, Bg + (size_t)row * K + ch * 4);
    }
}

template<int EPI>
__global__ __launch_bounds__(256, 2)
void mgemm_k(const float* __restrict__ A, const float* __restrict__ Bw,
             const float* __restrict__ bias, const float* __restrict__ res,
             float* __restrict__ C, int M, int N, int K)
{
    extern __shared__ float sm[];
    const uint32_t smb = smem_u32(sm);

    const int t = threadIdx.x, lane = t & 31, warp = t >> 5;
    const int wm = warp >> 1, wn = warp & 1;
    const int bm = blockIdx.x * BM, bn = blockIdx.y * BN;
    const int nk = K / BK;
    const int r = lane >> 2, cq = lane & 3;

    float acc[2][8][4];
#pragma unroll
    for (int i = 0; i < 2; i++)
#pragma unroll
        for (int j = 0; j < 8; j++)
#pragma unroll
            for (int q = 0; q < 4; q++) acc[i][j][q] = 0.f;

    const float* Abase = A + (size_t)bm * K;
    const float* Bbase = Bw + (size_t)bn * K;

#pragma unroll
    for (int s = 0; s < STG - 1; s++) {
        load_tile(Abase + s * BK, Bbase + s * BK, K,
                  smb + s * STAGE_F * 4, smb + (s * STAGE_F + ASZ) * 4, t);
        CP_COMMIT();
    }

    for (int kt = 0; kt < nk; kt++) {
        CP_WAIT1();
        __syncthreads();
        const int pf = kt + STG - 1;
        if (pf < nk) {
            const int st = pf % STG;
            load_tile(Abase + pf * BK, Bbase + pf * BK, K,
                      smb + st * STAGE_F * 4, smb + (st * STAGE_F + ASZ) * 4, t);
        }
        CP_COMMIT();

        const float* sA = sm + (kt % STG) * STAGE_F;
        const float* sB = sA + ASZ;
#pragma unroll
        for (int ks = 0; ks < 4; ks++) {
            const int k0 = ks * 8;
            float a[2][4];
#pragma unroll
            for (int mi = 0; mi < 2; mi++) {
                const int row = wm * 32 + mi * 16;
                a[mi][0] = sA[(row + r)     * APAD + k0 + cq];
                a[mi][1] = sA[(row + r + 8) * APAD + k0 + cq];
                a[mi][2] = sA[(row + r)     * APAD + k0 + cq + 4];
                a[mi][3] = sA[(row + r + 8) * APAD + k0 + cq + 4];
            }
            float b[8][2];
#pragma unroll
            for (int ni = 0; ni < 8; ni++) {
                const int col = wn * 64 + ni * 8;
                b[ni][0] = sB[(col + r) * APAD + k0 + cq];
                b[ni][1] = sB[(col + r) * APAD + k0 + cq + 4];
            }
#pragma unroll
            for (int mi = 0; mi < 2; mi++)
#pragma unroll
                for (int ni = 0; ni < 8; ni++)
                    mma_tf32(acc[mi][ni], a[mi][0], a[mi][1], a[mi][2], a[mi][3],
                             b[ni][0], b[ni][1]);
        }
    }

    // epilogue
#pragma unroll
    for (int ni = 0; ni < 8; ni++) {
        const int col = bn + wn * 64 + ni * 8 + cq * 2;
        const float b0 = bias[col], b1 = bias[col + 1];
#pragma unroll
        for (int mi = 0; mi < 2; mi++) {
            const int row0 = bm + wm * 32 + mi * 16 + r;
#pragma unroll
            for (int h = 0; h < 2; h++) {
                const int row = row0 + h * 8;
                float2 o;
                o.x = acc[mi][ni][h * 2 + 0] + b0;
                o.y = acc[mi][ni][h * 2 + 1] + b1;
                const size_t off = (size_t)row * N + col;
                if (EPI == 1) {
                    const float2 rr = *(const float2*)(res + off);
                    o.x += rr.x; o.y += rr.y;
                }
                if (EPI == 2) {
                    o.x = rnd_tf32(0.5f * o.x * (1.f + erff(o.x * 0.70710678118654752f)));
                    o.y = rnd_tf32(0.5f * o.y * (1.f + erff(o.y * 0.70710678118654752f)));
                }
                *(float2*)(C + off) = o;
            }
        }
    }
}

// ---------------- window attention ----------------
__global__ __launch_bounds__(256)
void win_attn_k(const float* __restrict__ qkv, const float* __restrict__ rel_table,
                const int* __restrict__ rel_idx, float* __restrict__ out)
{
    const int win = blockIdx.x;
    const int h   = blockIdx.y;
    const int b   = win >> 8;
    const int wr  = (win >> 4) & 15;
    const int wc  = win & 15;

    __shared__ float q[64][33], k[64][33], v[64][33];
    __shared__ float s[64][65];

    const int t = threadIdx.x;
#pragma unroll
    for (int i = 0; i < 8; i++) {
        int e = i * 256 + t;
        int tok = e >> 5, d = e & 31;
        int ti = tok >> 3, tj = tok & 7;
        size_t row = ((size_t)(b * 128 + wr * 8 + ti) * 128 + (wc * 8 + tj));
        const float* base = qkv + row * 768 + h * 32 + d;
        q[tok][d] = base[0];
        k[tok][d] = base[256];
        v[tok][d] = base[512];
    }
    __syncthreads();

    const int qi = t >> 2;
    const int j0 = (t & 3) * 16;
#pragma unroll
    for (int j = j0; j < j0 + 16; j++) {
        float a = 0.f;
#pragma unroll
        for (int d = 0; d < 32; d++) a = fmaf(q[qi][d], k[j][d], a);
        s[qi][j] = a * SCALE_ + rel_table[rel_idx[qi * 64 + j] * HEADS + h];
    }
    __syncthreads();

    const int warp = t >> 5, lane = t & 31;
    for (int r = warp * 8; r < warp * 8 + 8; r++) {
        float a = s[r][lane], bvv = s[r][lane + 32];
        float mx = fmaxf(a, bvv);
#pragma unroll
        for (int o = 16; o; o >>= 1) mx = fmaxf(mx, __shfl_xor_sync(0xffffffffu, mx, o));
        a = __expf(a - mx); bvv = __expf(bvv - mx);
        float sum = a + bvv;
#pragma unroll
        for (int o = 16; o; o >>= 1) sum += __shfl_xor_sync(0xffffffffu, sum, o);
        float inv = 1.f / sum;
        s[r][lane] = a * inv; s[r][lane + 32] = bvv * inv;
    }
    __syncthreads();

    const int d0 = (t & 3) * 8;
    float acc[8];
#pragma unroll
    for (int dd = 0; dd < 8; dd++) acc[dd] = 0.f;
    for (int j = 0; j < 64; j++) {
        float p = s[qi][j];
#pragma unroll
        for (int dd = 0; dd < 8; dd++) acc[dd] = fmaf(p, v[j][d0 + dd], acc[dd]);
    }
    int ti = qi >> 3, tj = qi & 7;
    size_t row = ((size_t)(b * 128 + wr * 8 + ti) * 128 + (wc * 8 + tj));
    float* ob = out + row * 256 + h * 32 + d0;
#pragma unroll
    for (int dd = 0; dd < 8; dd++) ob[dd] = acc[dd];
}

// ---------------- add + LN (ln rounded) ----------------
__global__ __launch_bounds__(256)
void add_ln_k(const float* __restrict__ x, const float* __restrict__ a,
              const float* __restrict__ w, const float* __restrict__ bb,
              float* __restrict__ xo, float* __restrict__ lo)
{
    const int warp = threadIdx.x >> 5, lane = threadIdx.x & 31;
    const size_t tok = (size_t)blockIdx.x * 8 + warp;
    const float* xr = x + tok * 256;
    const float* ar = a + tok * 256;
    float v[8]; float sum = 0.f;
#pragma unroll
    for (int i = 0; i < 8; i++) { int c = i * 32 + lane; v[i] = xr[c] + ar[c]; sum += v[i]; }
#pragma unroll
    for (int o = 16; o; o >>= 1) sum += __shfl_xor_sync(0xffffffffu, sum, o);
    float mean = sum * (1.f / 256.f);
    float s2 = 0.f;
#pragma unroll
    for (int i = 0; i < 8; i++) { float d = v[i] - mean; s2 += d * d; }
#pragma unroll
    for (int o = 16; o; o >>= 1) s2 += __shfl_xor_sync(0xffffffffu, s2, o);
    float rstd = rsqrtf(s2 * (1.f / 256.f) + 1e-5f);
    float* xr2 = xo + tok * 256;
    float* lr  = lo + tok * 256;
#pragma unroll
    for (int i = 0; i < 8; i++) {
        int c = i * 32 + lane;
        xr2[c] = v[i];
        lr[c]  = rnd_tf32((v[i] - mean) * rstd * w[c] + bb[c]);
    }
}

// ---------------- LN only ----------------
template<int RND>
__global__ __launch_bounds__(256)
void ln_k(const float* __restrict__ x, const float* __restrict__ w,
          const float* __restrict__ bb, float* __restrict__ lo)
{
    const int warp = threadIdx.x >> 5, lane = threadIdx.x & 31;
    const size_t tok = (size_t)blockIdx.x * 8 + warp;
    const float* xr = x + tok * 256;
    float v[8]; float sum = 0.f;
#pragma unroll
    for (int i = 0; i < 8; i++) { int c = i * 32 + lane; v[i] = xr[c]; sum += v[i]; }
#pragma unroll
    for (int o = 16; o; o >>= 1) sum += __shfl_xor_sync(0xffffffffu, sum, o);
    float mean = sum * (1.f / 256.f);
    float s2 = 0.f;
#pragma unroll
    for (int i = 0; i < 8; i++) { float d = v[i] - mean; s2 += d * d; }
#pragma unroll
    for (int o = 16; o; o >>= 1) s2 += __shfl_xor_sync(0xffffffffu, s2, o);
    float rstd = rsqrtf(s2 * (1.f / 256.f) + 1e-5f);
    float* lr = lo + tok * 256;
#pragma unroll
    for (int i = 0; i < 8; i++) {
        int c = i * 32 + lane;
        float o = (v[i] - mean) * rstd * w[c] + bb[c];
        lr[c] = RND ? rnd_tf32(o) : o;
    }
}

// ---------------- pool + sine pos (rounded) ----------------
__global__ __launch_bounds__(256)
void pool_pos_k(const float* __restrict__ x, float* __restrict__ out)
{
    const int blk = blockIdx.x;
    const int b  = blk >> 8;
    const int ph = (blk >> 4) & 15;
    const int pw = blk & 15;
    const int c  = threadIdx.x;

    size_t base = ((size_t)(b * 128 + ph * 8) * 128 + pw * 8) * 256 + c;
    float s = 0.f;
#pragma unroll
    for (int i = 0; i < 8; i++)
#pragma unroll
        for (int j = 0; j < 8; j++)
            s += x[base + ((size_t)i * 128 + j) * 256];
    s *= (1.f / 64.f);

    float e; int cc;
    if (c < 128) { e = (float)(ph + 1); cc = c; }
    else         { e = (float)(pw + 1); cc = c - 128; }
    e = e / (16.f + 1e-5f) * 6.283185307179586f;
    float expo = (float)(cc & ~1) / 128.f;
    float tt = powf(10000.f, expo);
    float p = e / tt;
    float pe = (cc & 1) ? cosf(p) : sinf(p);
    out[(size_t)blk * 256 + c] = rnd_tf32(s + pe);
}

// ---------------- global attention ----------------
__global__ __launch_bounds__(256)
void glob_attn_k(const float* __restrict__ qkv, float* __restrict__ out)
{
    const int b = blockIdx.x >> 3;
    const int h = blockIdx.x & 7;
    __shared__ float ks[64][32], vs[64][32];

    const int t = threadIdx.x;
    float q[32];
    const float* qp = qkv + ((size_t)(b * 256 + t)) * 768 + h * 32;
#pragma unroll
    for (int d = 0; d < 32; d++) q[d] = qp[d] * SCALE_;

    float m = -1e30f, l = 0.f, acc[32];
#pragma unroll
    for (int d = 0; d < 32; d++) acc[d] = 0.f;

    for (int c0 = 0; c0 < 256; c0 += 64) {
        __syncthreads();
#pragma unroll
        for (int i = 0; i < 8; i++) {
            int e = i * 256 + t;
            int tk = e >> 5, d = e & 31;
            const float* p = qkv + ((size_t)(b * 256 + c0 + tk)) * 768 + h * 32 + d;
            ks[tk][d] = p[256];
            vs[tk][d] = p[512];
        }
        __syncthreads();
        for (int j = 0; j < 64; j++) {
            float sc = 0.f;
#pragma unroll
            for (int d = 0; d < 32; d++) sc = fmaf(q[d], ks[j][d], sc);
            float mn = fmaxf(m, sc);
            float corr = __expf(m - mn);
            float p = __expf(sc - mn);
            l = l * corr + p;
#pragma unroll
            for (int d = 0; d < 32; d++) acc[d] = acc[d] * corr + p * vs[j][d];
            m = mn;
        }
    }
    float inv = 1.f / l;
    float* op = out + ((size_t)(b * 256 + t)) * 256 + h * 32;
#pragma unroll
    for (int d = 0; d < 32; d++) op[d] = acc[d] * inv;
}

// ---------------- upsample + add + LN (ln rounded) ----------------
__global__ __launch_bounds__(256)
void up_add_ln_k(float* __restrict__ x, const float* __restrict__ g,
                 const float* __restrict__ w, const float* __restrict__ bb,
                 float* __restrict__ lo)
{
    const int warp = threadIdx.x >> 5, lane = threadIdx.x & 31;
    const size_t tok = (size_t)blockIdx.x * 8 + warp;
    const int b  = (int)(tok >> 14);
    const int y  = (int)((tok >> 7) & 127);
    const int xx = (int)(tok & 127);

    float sy = (float)y  * (15.f / 127.f);
    float sx = (float)xx * (15.f / 127.f);
    int y0 = (int)floorf(sy); if (y0 > 15) y0 = 15;
    int x0 = (int)floorf(sx); if (x0 > 15) x0 = 15;
    float ty = sy - (float)y0, tx = sx - (float)x0;
    int y1 = min(y0 + 1, 15), x1 = min(x0 + 1, 15);

    const float* g00 = g + ((size_t)((b * 16 + y0) * 16 + x0)) * 256;
    const float* g01 = g + ((size_t)((b * 16 + y0) * 16 + x1)) * 256;
    const float* g10 = g + ((size_t)((b * 16 + y1) * 16 + x0)) * 256;
    const float* g11 = g + ((size_t)((b * 16 + y1) * 16 + x1)) * 256;
    float w00 = (1.f - ty) * (1.f - tx), w01 = (1.f - ty) * tx;
    float w10 = ty * (1.f - tx),         w11 = ty * tx;

    float* xr = x + tok * 256;
    float v[8]; float sum = 0.f;
#pragma unroll
    for (int i = 0; i < 8; i++) {
        int c = i * 32 + lane;
        float up = g00[c] * w00 + g01[c] * w01 + g10[c] * w10 + g11[c] * w11;
        v[i] = xr[c] + up;
        sum += v[i];
    }
#pragma unroll
    for (int o = 16; o; o >>= 1) sum += __shfl_xor_sync(0xffffffffu, sum, o);
    float mean = sum * (1.f / 256.f);
    float s2 = 0.f;
#pragma unroll
    for (int i = 0; i < 8; i++) { float d = v[i] - mean; s2 += d * d; }
#pragma unroll
    for (int o = 16; o; o >>= 1) s2 += __shfl_xor_sync(0xffffffffu, s2, o);
    float rstd = rsqrtf(s2 * (1.f / 256.f) + 1e-5f);
    float* lr = lo + tok * 256;
#pragma unroll
    for (int i = 0; i < 8; i++) {
        int c = i * 32 + lane;
        xr[c] = v[i];
        lr[c] = rnd_tf32((v[i] - mean) * rstd * w[c] + bb[c]);
    }
}

// ---------------- launch ----------------
static float* symaddr(const void* sym)
{
    void* p = nullptr;
    cudaGetSymbolAddress(&p, sym);
    return (float*)p;
}
static void round_arr(const float* in, float* out, int n)
{
    int n4 = n / 4;
    round4_k<<<(n4 + 255) / 256, 256>>>((const float4*)in, (float4*)out, n4);
}

extern "C" void kernel_launch(void* const* d_in, const int* in_sizes, int n_in,
                              void* d_out, int out_size)
{
    const float* x          = (const float*)d_in[0];
    const float* rel_table  = (const float*)d_in[1];
    const float* qkv_w      = (const float*)d_in[2];
    const float* qkv_b      = (const float*)d_in[3];
    const float* qkv2_w     = (const float*)d_in[4];
    const float* qkv2_b     = (const float*)d_in[5];
    const float* proj_ln_w  = (const float*)d_in[6];
    const float* proj_ln_b  = (const float*)d_in[7];
    const float* proj_w     = (const float*)d_in[8];
    const float* proj_b     = (const float*)d_in[9];
    const float* proj2_ln_w = (const float*)d_in[10];
    const float* proj2_ln_b = (const float*)d_in[11];
    const float* proj2_w    = (const float*)d_in[12];
    const float* proj2_b    = (const float*)d_in[13];
    const float* norm1_w    = (const float*)d_in[14];
    const float* norm1_b    = (const float*)d_in[15];
    const float* norm2_w    = (const float*)d_in[16];
    const float* norm2_b    = (const float*)d_in[17];
    const float* fc1_w      = (const float*)d_in[18];
    const float* fc1_b      = (const float*)d_in[19];
    const float* fc2_w      = (const float*)d_in[20];
    const float* fc2_b      = (const float*)d_in[21];
    const int*   rel_idx    = (const int*)  d_in[22];

    float* qkv   = symaddr(g_qkv);
    float* attn  = symaddr(g_attn);
    float* xb    = symaddr(g_x);
    float* ln    = symaddr(g_ln);
    float* hbuf  = symaddr(g_h);
    float* pool  = symaddr(g_pool);
    float* qkvg  = symaddr(g_qkvg);
    float* attng = symaddr(g_attng);
    float* wr    = symaddr(g_wr);

    cudaFuncSetAttribute(mgemm_k<0>, cudaFuncAttributeMaxDynamicSharedMemorySize, MGEMM_SMEM);
    cudaFuncSetAttribute(mgemm_k<1>, cudaFuncAttributeMaxDynamicSharedMemorySize, MGEMM_SMEM);
    cudaFuncSetAttribute(mgemm_k<2>, cudaFuncAttributeMaxDynamicSharedMemorySize, MGEMM_SMEM);

    const int M = NTOK;

    // 0) pre-round weights + input x to tf32 (rna)
    round_arr(qkv_w,   wr + OFF_QKVW,  768 * 256);
    round_arr(proj_w,  wr + OFF_PROJW, 256 * 256);
    round_arr(proj2_w, wr + OFF_PROJ2W,256 * 256);
    round_arr(fc1_w,   wr + OFF_FC1W,  1024 * 256);
    round_arr(fc2_w,   wr + OFF_FC2W,  256 * 1024);
    round_arr(qkv2_w,  wr + OFF_QKV2W, 768 * 256);
    round_arr(x, attn, M * 256);

    // 1) window-branch QKV
    mgemm_k<0><<<dim3(M/128, 6), 256, MGEMM_SMEM>>>(attn, wr + OFF_QKVW, qkv_b, nullptr, qkv, M, 768, 256);
    // 2) window attention
    win_attn_k<<<dim3(2048, 8), 256>>>(qkv, rel_table, rel_idx, attn);
    // 3) x = x + attn ; ln = LN(x)
    add_ln_k<<<M/8, 256>>>(x, attn, proj_ln_w, proj_ln_b, xb, ln);
    // 4) x += ln @ proj_w^T + proj_b
    mgemm_k<1><<<dim3(M/128, 2), 256, MGEMM_SMEM>>>(ln, wr + OFF_PROJW, proj_b, xb, xb, M, 256, 256);
    // 5) pool + sine pos
    pool_pos_k<<<2048, 256>>>(xb, pool);
    // 6) global QKV
    mgemm_k<0><<<dim3(16, 6), 256, MGEMM_SMEM>>>(pool, wr + OFF_QKV2W, qkv2_b, nullptr, qkvg, 2048, 768, 256);
    // 7) global attention
    glob_attn_k<<<64, 256>>>(qkvg, attng);
    // 8) x += upsample(attng) ; ln = LN(x)
    up_add_ln_k<<<M/8, 256>>>(xb, attng, proj2_ln_w, proj2_ln_b, ln);
    // 9) x += ln @ proj2_w^T + proj2_b
    mgemm_k<1><<<dim3(M/128, 2), 256, MGEMM_SMEM>>>(ln, wr + OFF_PROJ2W, proj2_b, xb, xb, M, 256, 256);
    // 10) ln = LN(x, norm1)
    ln_k<1><<<M/8, 256>>>(xb, norm1_w, norm1_b, ln);
    // 11) h = gelu(ln @ fc1^T)
    mgemm_k<2><<<dim3(M/128, 8), 256, MGEMM_SMEM>>>(ln, wr + OFF_FC1W, fc1_b, nullptr, hbuf, M, 1024, 256);
    // 12) x += h @ fc2^T
    mgemm_k<1><<<dim3(M/128, 2), 256, MGEMM_SMEM>>>(hbuf, wr + OFF_FC2W, fc2_b, xb, xb, M, 256, 1024);
    // 13) out = LN(x, norm2)
    ln_k<0><<<M/8, 256>>>(xb, norm2_w, norm2_b, (float*)d_out);
}